// round 12
// baseline (speedup 1.0000x reference)
#include <cuda_runtime.h>
#include <math.h>

// Problem constants
constexpr int CB = 512;        // batch
constexpr int CK = 25;         // nodes per board (incl. anchor node 0)
constexpr int CH = 256;        // hidden
constexpr int CSTEPS = 32;
constexpr int CN = CB * CK;    // 12800 nodes
constexpr int CNH = CN * CH;   // 3276800

// Scratch (device globals; no allocation allowed)
__device__ float g_x[CNH];             // lstm_emb (constant x)
__device__ float g_h[CNH];             // hidden state
__device__ float g_c[CNH];             // cell state
__device__ float g_gx[CN * 1024];      // chain prefix: x @ W_ih[:, :256].T
__device__ float g_A[CNH];             // per-step A = h @ W1^T
__device__ float g_m[CNH];             // per-step messages
__device__ float g_t2[CN * 1024];      // per-step t2 = h @ W_hh^T
__device__ float g_gates[CN * 1024];   // gates
__device__ float g_W2T[256 * 256];     // W2 transposed
__device__ float g_oe[CNH];            // output_embeddings
__device__ float g_red[CSTEPS * CB + CB];  // per-block gol partials

// ---------------------------------------------------------------------------
// Packed f32x2 helpers (Blackwell FFMA2) — bitwise identical per lane to scalar.
typedef unsigned long long u64;
__device__ __forceinline__ u64 pk2(float lo, float hi)
{
    u64 r; asm("mov.b64 %0, {%1, %2};" : "=l"(r) : "f"(lo), "f"(hi)); return r;
}
__device__ __forceinline__ float2 up2(u64 v)
{
    float2 f; asm("mov.b64 {%0, %1}, %2;" : "=f"(f.x), "=f"(f.y) : "l"(v)); return f;
}
__device__ __forceinline__ u64 ffma2(u64 a, u64 b, u64 c)
{
    u64 d; asm("fma.rn.f32x2 %0, %1, %2, %3;" : "=l"(d) : "l"(a), "l"(b), "l"(c));
    return d;
}

// ---------------------------------------------------------------------------
// XLA elementwise replicas (EmitFastTanh; logistic = 0.5 + 0.5*tanh(0.5x)).
__device__ __forceinline__ float xla_tanh(float x)
{
    float xc = fminf(fmaxf(x, -9.f), 9.f);
    float x2 = __fmul_rn(xc, xc);
    float np = fmaf(x2, -2.76076847742355e-16f, 2.00018790482477e-13f);
    np = fmaf(x2, np, -8.60467152213735e-11f);
    np = fmaf(x2, np,  5.12229709037114e-08f);
    np = fmaf(x2, np,  1.48572235717979e-05f);
    np = fmaf(x2, np,  6.37261928875436e-04f);
    np = fmaf(x2, np,  4.89352455891786e-03f);
    float num = __fmul_rn(xc, np);
    float dp = fmaf(x2, 1.19825839466702e-06f, 1.18534705686654e-04f);
    dp = fmaf(x2, dp, 2.26843463243900e-03f);
    dp = fmaf(x2, dp, 4.89352518554385e-03f);
    float r = __fdiv_rn(num, dp);
    return (fabsf(x) < 0.0004f) ? x : r;
}
__device__ __forceinline__ float xla_sigmoid(float x)
{
    return __fadd_rn(0.5f, __fmul_rn(0.5f, xla_tanh(__fmul_rn(0.5f, x))));
}

// ---------------------------------------------------------------------------
__global__ void prep_kernel(const float* __restrict__ Wmsg)
{
    int t = blockIdx.x * blockDim.x + threadIdx.x;
    if (t >= 256 * 256) return;
    int k = t >> 8, r = t & 255;
    g_W2T[k * 256 + r] = Wmsg[r * 512 + 256 + k];
}

// ---------------------------------------------------------------------------
__global__ void gather_init(const float* __restrict__ emb,
                            const int* __restrict__ perm,
                            float* __restrict__ out_lstm_emb)
{
    int gid = blockIdx.x * blockDim.x + threadIdx.x;
    if (gid >= CNH) return;
    int n = gid >> 8, h = gid & 255;
    float v = emb[(size_t)perm[n] * CH + h];
    g_x[gid] = v;
    out_lstm_emb[gid] = v;
    g_h[gid] = v;
    g_c[gid] = v;
    if (n % CK == 0) g_m[gid] = 0.f;   // node 0 never receives messages
}

// ---------------------------------------------------------------------------
// 256-thread GEMM tile (128x128 @ (by,bx)) of A[M,K] @ B[N,K]^T.
// One sequential fma chain over ascending k per output; FFMA2 lanes bitwise
// == scalar. M-paired accumulators; register double-buffered smem pipeline.
// Cinit != null : acc starts at Cinit (chain prefix).
// Cadd  != null : post-add (commutative).
__device__ __forceinline__ void sgemm_tile(
    int K,
    const float* __restrict__ A, int lda,
    const float* __restrict__ Bm, int ldb,
    float* __restrict__ C, int ldc,
    const float* __restrict__ Cinit,
    const float* __restrict__ Cadd,
    int bx, int by,
    float As[2][16][128], float Bs[2][16][128])
{
    const int tid = threadIdx.x;
    const int tx = tid & 15;
    const int ty = tid >> 4;
    const float* Ab = A + (size_t)by * 128 * lda;
    const float* Bb = Bm + (size_t)bx * 128 * ldb;
    const int lrow = tid >> 1;
    const int lk4b = (tid & 1) * 2;

    u64 acc2[4][8];   // [m-pair][j]; lanes = (row m0, row m1)
    if (Cinit) {
#pragma unroll
        for (int mp = 0; mp < 4; mp++) {
            int lr0 = (mp < 2) ? (ty * 4 + mp * 2) : (64 + ty * 4 + (mp - 2) * 2);
            size_t r0 = (size_t)by * 128 + lr0;
            const float* I0 = Cinit + r0 * ldc + (size_t)bx * 128;
            const float* I1 = I0 + ldc;
            float4 a0 = *(const float4*)(I0 + tx * 4);
            float4 a1 = *(const float4*)(I0 + 64 + tx * 4);
            float4 b0 = *(const float4*)(I1 + tx * 4);
            float4 b1 = *(const float4*)(I1 + 64 + tx * 4);
            acc2[mp][0] = pk2(a0.x, b0.x); acc2[mp][1] = pk2(a0.y, b0.y);
            acc2[mp][2] = pk2(a0.z, b0.z); acc2[mp][3] = pk2(a0.w, b0.w);
            acc2[mp][4] = pk2(a1.x, b1.x); acc2[mp][5] = pk2(a1.y, b1.y);
            acc2[mp][6] = pk2(a1.z, b1.z); acc2[mp][7] = pk2(a1.w, b1.w);
        }
    } else {
#pragma unroll
        for (int mp = 0; mp < 4; mp++)
#pragma unroll
            for (int j = 0; j < 8; j++) acc2[mp][j] = 0ull;
    }

    float4 avs[2], bvs[2];
#pragma unroll
    for (int u = 0; u < 2; u++) {
        int k4 = lk4b + u;
        avs[u] = *(const float4*)(Ab + (size_t)lrow * lda + k4 * 4);
        bvs[u] = *(const float4*)(Bb + (size_t)lrow * ldb + k4 * 4);
    }
#pragma unroll
    for (int u = 0; u < 2; u++) {
        int k4 = lk4b + u;
        As[0][k4 * 4 + 0][lrow] = avs[u].x;
        As[0][k4 * 4 + 1][lrow] = avs[u].y;
        As[0][k4 * 4 + 2][lrow] = avs[u].z;
        As[0][k4 * 4 + 3][lrow] = avs[u].w;
        Bs[0][k4 * 4 + 0][lrow] = bvs[u].x;
        Bs[0][k4 * 4 + 1][lrow] = bvs[u].y;
        Bs[0][k4 * 4 + 2][lrow] = bvs[u].z;
        Bs[0][k4 * 4 + 3][lrow] = bvs[u].w;
    }
    __syncthreads();

    const int T = K >> 4;
    int buf = 0;
    for (int t = 0; t < T; t++) {
        if (t + 1 < T) {
            int kt = (t + 1) * 16;
#pragma unroll
            for (int u = 0; u < 2; u++) {
                int k4 = lk4b + u;
                avs[u] = *(const float4*)(Ab + (size_t)lrow * lda + kt + k4 * 4);
                bvs[u] = *(const float4*)(Bb + (size_t)lrow * ldb + kt + k4 * 4);
            }
        }
#pragma unroll
        for (int k = 0; k < 16; k++) {
            u64 ap[4];
            ap[0] = *(const u64*)(&As[buf][k][ty * 4]);
            ap[1] = *(const u64*)(&As[buf][k][ty * 4 + 2]);
            ap[2] = *(const u64*)(&As[buf][k][64 + ty * 4]);
            ap[3] = *(const u64*)(&As[buf][k][64 + ty * 4 + 2]);
            float b[8];
            *(float4*)(b)     = *(const float4*)(&Bs[buf][k][tx * 4]);
            *(float4*)(b + 4) = *(const float4*)(&Bs[buf][k][64 + tx * 4]);
#pragma unroll
            for (int j = 0; j < 8; j++) {
                u64 bd = pk2(b[j], b[j]);
#pragma unroll
                for (int mp = 0; mp < 4; mp++)
                    acc2[mp][j] = ffma2(ap[mp], bd, acc2[mp][j]);
            }
        }
        if (t + 1 < T) {
            int nb = buf ^ 1;
#pragma unroll
            for (int u = 0; u < 2; u++) {
                int k4 = lk4b + u;
                As[nb][k4 * 4 + 0][lrow] = avs[u].x;
                As[nb][k4 * 4 + 1][lrow] = avs[u].y;
                As[nb][k4 * 4 + 2][lrow] = avs[u].z;
                As[nb][k4 * 4 + 3][lrow] = avs[u].w;
                Bs[nb][k4 * 4 + 0][lrow] = bvs[u].x;
                Bs[nb][k4 * 4 + 1][lrow] = bvs[u].y;
                Bs[nb][k4 * 4 + 2][lrow] = bvs[u].z;
                Bs[nb][k4 * 4 + 3][lrow] = bvs[u].w;
            }
            __syncthreads();
            buf = nb;
        }
    }

#pragma unroll
    for (int mp = 0; mp < 4; mp++) {
        int lr0 = (mp < 2) ? (ty * 4 + mp * 2) : (64 + ty * 4 + (mp - 2) * 2);
        size_t r0 = (size_t)by * 128 + lr0;
        float* C0 = C + r0 * ldc + (size_t)bx * 128;
        float* C1 = C0 + ldc;
        float2 p[8];
#pragma unroll
        for (int j = 0; j < 8; j++) p[j] = up2(acc2[mp][j]);
        float4 v00 = make_float4(p[0].x, p[1].x, p[2].x, p[3].x);
        float4 v01 = make_float4(p[4].x, p[5].x, p[6].x, p[7].x);
        float4 v10 = make_float4(p[0].y, p[1].y, p[2].y, p[3].y);
        float4 v11 = make_float4(p[4].y, p[5].y, p[6].y, p[7].y);
        if (Cadd) {
            const float* A0 = Cadd + r0 * ldc + (size_t)bx * 128;
            const float* A1 = A0 + ldc;
            float4 c00 = *(const float4*)(A0 + tx * 4);
            float4 c01 = *(const float4*)(A0 + 64 + tx * 4);
            float4 c10 = *(const float4*)(A1 + tx * 4);
            float4 c11 = *(const float4*)(A1 + 64 + tx * 4);
            v00.x = __fadd_rn(v00.x, c00.x); v00.y = __fadd_rn(v00.y, c00.y);
            v00.z = __fadd_rn(v00.z, c00.z); v00.w = __fadd_rn(v00.w, c00.w);
            v01.x = __fadd_rn(v01.x, c01.x); v01.y = __fadd_rn(v01.y, c01.y);
            v01.z = __fadd_rn(v01.z, c01.z); v01.w = __fadd_rn(v01.w, c01.w);
            v10.x = __fadd_rn(v10.x, c10.x); v10.y = __fadd_rn(v10.y, c10.y);
            v10.z = __fadd_rn(v10.z, c10.z); v10.w = __fadd_rn(v10.w, c10.w);
            v11.x = __fadd_rn(v11.x, c11.x); v11.y = __fadd_rn(v11.y, c11.y);
            v11.z = __fadd_rn(v11.z, c11.z); v11.w = __fadd_rn(v11.w, c11.w);
        }
        *(float4*)(C0 + tx * 4) = v00;
        *(float4*)(C0 + 64 + tx * 4) = v01;
        *(float4*)(C1 + tx * 4) = v10;
        *(float4*)(C1 + 64 + tx * 4) = v11;
    }
}

__global__ __launch_bounds__(256, 2) void sgemm_nt(
    int K,
    const float* __restrict__ A, int lda,
    const float* __restrict__ Bm, int ldb,
    float* __restrict__ C, int ldc,
    const float* __restrict__ Cinit,
    const float* __restrict__ Cadd)
{
    __shared__ float As[2][16][128];
    __shared__ float Bs[2][16][128];
    sgemm_tile(K, A, lda, Bm, ldb, C, ldc, Cinit, Cadd,
               blockIdx.x, blockIdx.y, As, Bs);
}

// ---------------------------------------------------------------------------
// 128-thread GEMM tile (128x64 @ (by,bx)), K=256. Same per-output ascending-k
// chains (bitwise identical to the 256-thread tile; only thread mapping
// differs). Used for t2 tiles fused into the msg launch.
struct Sm64 { float As[2][16][128]; float Bs[2][16][64]; };

__device__ __forceinline__ void gemm64_tile(
    const float* __restrict__ A, int lda,
    const float* __restrict__ Bm, int ldb,
    float* __restrict__ C, int ldc,
    int bx, int by, Sm64& sm)
{
    const int tid = threadIdx.x;           // 0..127
    const int tx = tid & 7;                // 8 col groups
    const int ty = tid >> 3;               // 16 row groups
    const float* Ab = A + (size_t)by * 128 * lda;
    const float* Bb = Bm + (size_t)bx * 64 * ldb;
    const int browb = tid & 63;
    const int bk2 = (tid >> 6) * 2;        // k4 base for B loads

    u64 acc2[4][8];
#pragma unroll
    for (int mp = 0; mp < 4; mp++)
#pragma unroll
        for (int j = 0; j < 8; j++) acc2[mp][j] = 0ull;

    float4 avs[4], bvs[2];
#pragma unroll
    for (int k4 = 0; k4 < 4; k4++)
        avs[k4] = *(const float4*)(Ab + (size_t)tid * lda + k4 * 4);
#pragma unroll
    for (int u = 0; u < 2; u++)
        bvs[u] = *(const float4*)(Bb + (size_t)browb * ldb + (bk2 + u) * 4);
#pragma unroll
    for (int k4 = 0; k4 < 4; k4++) {
        sm.As[0][k4 * 4 + 0][tid] = avs[k4].x;
        sm.As[0][k4 * 4 + 1][tid] = avs[k4].y;
        sm.As[0][k4 * 4 + 2][tid] = avs[k4].z;
        sm.As[0][k4 * 4 + 3][tid] = avs[k4].w;
    }
#pragma unroll
    for (int u = 0; u < 2; u++) {
        int k4 = bk2 + u;
        sm.Bs[0][k4 * 4 + 0][browb] = bvs[u].x;
        sm.Bs[0][k4 * 4 + 1][browb] = bvs[u].y;
        sm.Bs[0][k4 * 4 + 2][browb] = bvs[u].z;
        sm.Bs[0][k4 * 4 + 3][browb] = bvs[u].w;
    }
    __syncthreads();

    const int T = 16;                       // K=256
    int buf = 0;
    for (int t = 0; t < T; t++) {
        if (t + 1 < T) {
            int kt = (t + 1) * 16;
#pragma unroll
            for (int k4 = 0; k4 < 4; k4++)
                avs[k4] = *(const float4*)(Ab + (size_t)tid * lda + kt + k4 * 4);
#pragma unroll
            for (int u = 0; u < 2; u++)
                bvs[u] = *(const float4*)(Bb + (size_t)browb * ldb + kt + (bk2 + u) * 4);
        }
#pragma unroll
        for (int k = 0; k < 16; k++) {
            u64 ap[4];
            ap[0] = *(const u64*)(&sm.As[buf][k][ty * 4]);
            ap[1] = *(const u64*)(&sm.As[buf][k][ty * 4 + 2]);
            ap[2] = *(const u64*)(&sm.As[buf][k][64 + ty * 4]);
            ap[3] = *(const u64*)(&sm.As[buf][k][64 + ty * 4 + 2]);
            float b[8];
            *(float4*)(b)     = *(const float4*)(&sm.Bs[buf][k][tx * 4]);
            *(float4*)(b + 4) = *(const float4*)(&sm.Bs[buf][k][32 + tx * 4]);
#pragma unroll
            for (int j = 0; j < 8; j++) {
                u64 bd = pk2(b[j], b[j]);
#pragma unroll
                for (int mp = 0; mp < 4; mp++)
                    acc2[mp][j] = ffma2(ap[mp], bd, acc2[mp][j]);
            }
        }
        if (t + 1 < T) {
            int nb = buf ^ 1;
#pragma unroll
            for (int k4 = 0; k4 < 4; k4++) {
                sm.As[nb][k4 * 4 + 0][tid] = avs[k4].x;
                sm.As[nb][k4 * 4 + 1][tid] = avs[k4].y;
                sm.As[nb][k4 * 4 + 2][tid] = avs[k4].z;
                sm.As[nb][k4 * 4 + 3][tid] = avs[k4].w;
            }
#pragma unroll
            for (int u = 0; u < 2; u++) {
                int k4 = bk2 + u;
                sm.Bs[nb][k4 * 4 + 0][browb] = bvs[u].x;
                sm.Bs[nb][k4 * 4 + 1][browb] = bvs[u].y;
                sm.Bs[nb][k4 * 4 + 2][browb] = bvs[u].z;
                sm.Bs[nb][k4 * 4 + 3][browb] = bvs[u].w;
            }
            __syncthreads();
            buf = nb;
        }
    }

#pragma unroll
    for (int mp = 0; mp < 4; mp++) {
        int lr0 = (mp < 2) ? (ty * 4 + mp * 2) : (64 + ty * 4 + (mp - 2) * 2);
        size_t r0 = (size_t)by * 128 + lr0;
        float* C0 = C + r0 * ldc + (size_t)bx * 64;
        float* C1 = C0 + ldc;
        float2 p[8];
#pragma unroll
        for (int j = 0; j < 8; j++) p[j] = up2(acc2[mp][j]);
        *(float4*)(C0 + tx * 4)      = make_float4(p[0].x, p[1].x, p[2].x, p[3].x);
        *(float4*)(C0 + 32 + tx * 4) = make_float4(p[4].x, p[5].x, p[6].x, p[7].x);
        *(float4*)(C1 + tx * 4)      = make_float4(p[0].y, p[1].y, p[2].y, p[3].y);
        *(float4*)(C1 + 32 + tx * 4) = make_float4(p[4].y, p[5].y, p[6].y, p[7].y);
    }
}

// ---------------------------------------------------------------------------
// msg body (exact per-edge chains, FFMA2) — unchanged arithmetic.
__device__ __forceinline__ void msg_body(int j, int b, float hj[256])
{
    const int base = b * CK + 1;
    const int rh = threadIdx.x;

    hj[rh]       = g_h[(size_t)(base + j) * CH + rh];
    hj[rh + 128] = g_h[(size_t)(base + j) * CH + rh + 128];
    __syncthreads();

    u64 acc[24];
#pragma unroll
    for (int i = 0; i < 24; i++)
        acc[i] = *(const u64*)(&g_A[(size_t)(base + i) * CH + 2 * rh]);

    const u64* w2p = (const u64*)g_W2T + rh;
#pragma unroll 4
    for (int k = 0; k < 256; k++) {
        u64 w = w2p[(size_t)k * 128];
        float hk = hj[k];
        u64 h2 = pk2(hk, hk);
#pragma unroll
        for (int i = 0; i < 24; i++)
            acc[i] = ffma2(h2, w, acc[i]);
    }

    float mlo = 0.f, mhi = 0.f;
#pragma unroll
    for (int i = 0; i < 24; i++)
        if (i != j) {
            float2 e = up2(acc[i]);
            mlo = __fadd_rn(mlo, fmaxf(e.x, 0.f));
            mhi = __fadd_rn(mhi, fmaxf(e.y, 0.f));
        }
    *(float2*)(&g_m[(size_t)(base + j) * CH + 2 * rh]) = make_float2(mlo, mhi);
}

// Fused: blocks 0..1599 compute t2 = h @ W_hh^T (16x100 tiles of 128x64);
// blocks 1600.. compute per-edge msg chains. t2 blocks schedule first and
// hide under the msg issue-floor time (t2 independent of msg).
__global__ __launch_bounds__(128) void msg_t2(const float* __restrict__ Whh)
{
    __shared__ union { Sm64 g; float hj[256]; } sm;
    int bid = blockIdx.x;
    if (bid < 1600) {
        gemm64_tile(g_h, 256, Whh, 256, g_t2, 1024,
                    bid & 15, bid >> 4, sm.g);
    } else {
        int i = bid - 1600;
        msg_body(i % 24, i / 24, sm.hj);
    }
}

// ---------------------------------------------------------------------------
// LSTM pointwise, float4-vectorized on internal buffers; scalar stores to the
// (4B-aligned) output slice.
__global__ void lstm_step(float* __restrict__ hs_slice)
{
    int t = blockIdx.x * blockDim.x + threadIdx.x;
    if (t >= CNH / 4) return;
    int n = t >> 6;
    int h4 = t & 63;
    const float4* g = (const float4*)(g_gates + (size_t)n * 1024);
    float4 ig = g[h4], fg = g[64 + h4], gg = g[128 + h4], og = g[192 + h4];
    float4 c = *(const float4*)(g_c + (size_t)t * 4);
    float4 nc, nh;
    {
        float si = xla_sigmoid(ig.x), sf = xla_sigmoid(fg.x), so = xla_sigmoid(og.x);
        nc.x = __fadd_rn(__fmul_rn(sf, c.x), __fmul_rn(si, xla_tanh(gg.x)));
        nh.x = __fmul_rn(so, xla_tanh(nc.x));
    }
    {
        float si = xla_sigmoid(ig.y), sf = xla_sigmoid(fg.y), so = xla_sigmoid(og.y);
        nc.y = __fadd_rn(__fmul_rn(sf, c.y), __fmul_rn(si, xla_tanh(gg.y)));
        nh.y = __fmul_rn(so, xla_tanh(nc.y));
    }
    {
        float si = xla_sigmoid(ig.z), sf = xla_sigmoid(fg.z), so = xla_sigmoid(og.z);
        nc.z = __fadd_rn(__fmul_rn(sf, c.z), __fmul_rn(si, xla_tanh(gg.z)));
        nh.z = __fmul_rn(so, xla_tanh(nc.z));
    }
    {
        float si = xla_sigmoid(ig.w), sf = xla_sigmoid(fg.w), so = xla_sigmoid(og.w);
        nc.w = __fadd_rn(__fmul_rn(sf, c.w), __fmul_rn(si, xla_tanh(gg.w)));
        nh.w = __fmul_rn(so, xla_tanh(nc.w));
    }
    *(float4*)(g_c + (size_t)t * 4) = nc;
    *(float4*)(g_h + (size_t)t * 4) = nh;
    float* hp = hs_slice + (size_t)t * 4;
    hp[0] = nh.x; hp[1] = nh.y; hp[2] = nh.z; hp[3] = nh.w;
}

// ---------------------------------------------------------------------------
__global__ void finalize_emb(float* __restrict__ o_in, float* __restrict__ o_out)
{
    int gid = blockIdx.x * blockDim.x + threadIdx.x;
    if (gid >= CNH) return;
    int n = gid >> 8;
    bool anchor = (n % CK) == 0;
    float xv = g_x[gid];
    float hv = g_h[gid];
    float ov = g_oe[gid];
    o_in[gid]  = anchor ? xv : hv;
    o_out[gid] = anchor ? xv : ov;
}

// ---------------------------------------------------------------------------
__global__ __launch_bounds__(256) void gol_kernel(const float* __restrict__ src, int out_base)
{
    __shared__ float hn[24][257];
    __shared__ float nrm[24];
    __shared__ float red[256];
    const int tid = threadIdx.x;
    const size_t rowbase = (size_t)blockIdx.x * 25 + 1;
    for (int idx = tid; idx < 24 * 256; idx += 256) {
        int i = idx >> 8, k = idx & 255;
        hn[i][k] = src[(rowbase + i) * 256 + k];
    }
    __syncthreads();
    if (tid < 24) {
        float s = 0.f;
        for (int k = 0; k < 256; k++) { float v = hn[tid][k]; s += v * v; }
        nrm[tid] = 1.f / (sqrtf(s) + 1e-8f);
    }
    __syncthreads();
    for (int idx = tid; idx < 24 * 256; idx += 256) {
        int i = idx >> 8, k = idx & 255;
        hn[i][k] *= nrm[i];
    }
    __syncthreads();
    float local = 0.f;
    for (int p = tid; p < 276; p += 256) {
        int i = 0, pp = p;
        while (pp >= 23 - i) { pp -= 23 - i; i++; }
        int j = i + 1 + pp;
        float d = 0.f;
#pragma unroll 8
        for (int k = 0; k < 256; k++) d += hn[i][k] * hn[j][k];
        local += fabsf(d);
    }
    red[tid] = local;
    __syncthreads();
    for (int s = 128; s > 0; s >>= 1) {
        if (tid < s) red[tid] += red[tid + s];
        __syncthreads();
    }
    if (tid == 0) g_red[out_base + blockIdx.x] = red[0] * (2.f / (24.f * 23.f));
}

__global__ void gol_finalize(float* __restrict__ out)
{
    __shared__ double red[256];
    int tid = threadIdx.x;
    double s1 = 0.0, s2 = 0.0;
    for (int i = tid; i < CSTEPS * CB; i += 256) s1 += (double)g_red[i];
    for (int i = tid; i < CB; i += 256) s2 += (double)g_red[CSTEPS * CB + i];
    red[tid] = s1 / (double)(CSTEPS * CB) + s2 / (double)CB;
    __syncthreads();
    for (int s = 128; s > 0; s >>= 1) {
        if (tid < s) red[tid] += red[tid + s];
        __syncthreads();
    }
    if (tid == 0) out[0] = (float)red[0];
}

// ---------------------------------------------------------------------------
extern "C" void kernel_launch(void* const* d_in, const int* in_sizes, int n_in,
                              void* d_out, int out_size)
{
    (void)in_sizes; (void)n_in; (void)out_size;
    const float* emb  = (const float*)d_in[0];
    const float* Wmsg = (const float*)d_in[1];
    const float* Wih  = (const float*)d_in[2];
    const float* Whh  = (const float*)d_in[3];
    const float* Wout = (const float*)d_in[4];
    const int*   perm = (const int*)d_in[5];

    float* out = (float*)d_out;
    float* o_gol  = out;
    float* o_lstm = out + 1;
    float* o_in   = out + 1 + (size_t)CNH;
    float* o_out  = out + 1 + 2 * (size_t)CNH;
    float* o_hs   = out + 1 + 3 * (size_t)CNH;

    float *px, *ph, *pgx, *pA, *pm, *pt2, *pgates, *poe;
    cudaGetSymbolAddress((void**)&px,     g_x);
    cudaGetSymbolAddress((void**)&ph,     g_h);
    cudaGetSymbolAddress((void**)&pgx,    g_gx);
    cudaGetSymbolAddress((void**)&pA,     g_A);
    cudaGetSymbolAddress((void**)&pm,     g_m);
    cudaGetSymbolAddress((void**)&pt2,    g_t2);
    cudaGetSymbolAddress((void**)&pgates, g_gates);
    cudaGetSymbolAddress((void**)&poe,    g_oe);

    prep_kernel<<<256, 256>>>(Wmsg);
    gather_init<<<CNH / 256, 256>>>(emb, perm, o_lstm);

    // gx = x @ W_ih[:, :256]^T  — chain prefix of t1, reused every step
    sgemm_nt<<<dim3(8, CN / 128), 256>>>(256, px, 256, Wih, 512,
                                         pgx, 1024, nullptr, nullptr);

    for (int s = 0; s < CSTEPS; s++) {
        // A = h @ W1^T   (small; t2 no longer here — it's fused into msg)
        sgemm_nt<<<dim3(2, CN / 128), 256>>>(256, ph, 256, Wmsg, 512,
                                             pA, 256, nullptr, nullptr);
        // fused: t2 tiles (first, independent) + per-edge msg chains
        msg_t2<<<1600 + 24 * CB, 128>>>(Whh);
        // gates = chain(gx -> m terms) + t2   (post-add, commutative)
        sgemm_nt<<<dim3(8, CN / 128), 256>>>(256, pm, 256, Wih + 256, 512,
                                             pgates, 1024, pgx, pt2);
        lstm_step<<<CNH / 1024, 256>>>(o_hs + (size_t)s * CNH);
    }

    // output_embeddings = h_last @ W_out^T
    sgemm_nt<<<dim3(2, CN / 128), 256>>>(256, ph, 256, Wout, 256,
                                         poe, 256, nullptr, nullptr);
    finalize_emb<<<CNH / 256, 256>>>(o_in, o_out);

    gol_kernel<<<CSTEPS * CB, 256>>>(o_hs, 0);
    gol_kernel<<<CB, 256>>>(poe, CSTEPS * CB);
    gol_finalize<<<1, 256>>>(o_gol);
}

// round 13
// speedup vs baseline: 1.0808x; 1.0808x over previous
#include <cuda_runtime.h>
#include <math.h>

// Problem constants
constexpr int CB = 512;        // batch
constexpr int CK = 25;         // nodes per board (incl. anchor node 0)
constexpr int CH = 256;        // hidden
constexpr int CSTEPS = 32;
constexpr int CN = CB * CK;    // 12800 nodes
constexpr int CNH = CN * CH;   // 3276800

// Scratch (device globals; no allocation allowed)
__device__ float g_x[CNH];             // lstm_emb (constant x)
__device__ float g_h[CNH];             // hidden state
__device__ float g_c[CNH];             // cell state
__device__ float g_gx[CN * 1024];      // chain prefix: x @ Wx'^T (interleaved cols)
__device__ float g_A[CNH];             // per-step A = h @ W1^T
__device__ float g_m[CNH];             // per-step messages
__device__ float g_t2[CN * 1024];      // per-step t2 = h @ Wh'^T (interleaved cols)
__device__ float g_W2T[256 * 256];     // W2 transposed
__device__ float g_Wxp[1024 * 256];    // interleaved Wih[:, :256]:  row 4h+g
__device__ float g_Wmp[1024 * 256];    // interleaved Wih[:, 256:512]
__device__ float g_Whp[1024 * 256];    // interleaved Whh
__device__ float g_oe[CNH];            // output_embeddings
__device__ float g_red[CSTEPS * CB + CB];  // per-block gol partials

// ---------------------------------------------------------------------------
// Packed f32x2 helpers (Blackwell FFMA2) — bitwise identical per lane to scalar.
typedef unsigned long long u64;
__device__ __forceinline__ u64 pk2(float lo, float hi)
{
    u64 r; asm("mov.b64 %0, {%1, %2};" : "=l"(r) : "f"(lo), "f"(hi)); return r;
}
__device__ __forceinline__ float2 up2(u64 v)
{
    float2 f; asm("mov.b64 {%0, %1}, %2;" : "=f"(f.x), "=f"(f.y) : "l"(v)); return f;
}
__device__ __forceinline__ u64 ffma2(u64 a, u64 b, u64 c)
{
    u64 d; asm("fma.rn.f32x2 %0, %1, %2, %3;" : "=l"(d) : "l"(a), "l"(b), "l"(c));
    return d;
}

// ---------------------------------------------------------------------------
// XLA elementwise replicas (EmitFastTanh; logistic = 0.5 + 0.5*tanh(0.5x)).
__device__ __forceinline__ float xla_tanh(float x)
{
    float xc = fminf(fmaxf(x, -9.f), 9.f);
    float x2 = __fmul_rn(xc, xc);
    float np = fmaf(x2, -2.76076847742355e-16f, 2.00018790482477e-13f);
    np = fmaf(x2, np, -8.60467152213735e-11f);
    np = fmaf(x2, np,  5.12229709037114e-08f);
    np = fmaf(x2, np,  1.48572235717979e-05f);
    np = fmaf(x2, np,  6.37261928875436e-04f);
    np = fmaf(x2, np,  4.89352455891786e-03f);
    float num = __fmul_rn(xc, np);
    float dp = fmaf(x2, 1.19825839466702e-06f, 1.18534705686654e-04f);
    dp = fmaf(x2, dp, 2.26843463243900e-03f);
    dp = fmaf(x2, dp, 4.89352518554385e-03f);
    float r = __fdiv_rn(num, dp);
    return (fabsf(x) < 0.0004f) ? x : r;
}
__device__ __forceinline__ float xla_sigmoid(float x)
{
    return __fadd_rn(0.5f, __fmul_rn(0.5f, xla_tanh(__fmul_rn(0.5f, x))));
}

// One LSTM cell, identical arithmetic to the standalone lstm_step kernel.
__device__ __forceinline__ void lstm_cell(size_t row, int h,
                                          float ig, float fg, float gg, float og,
                                          float* __restrict__ hs)
{
    size_t idx = row * 256 + (size_t)h;
    float c = g_c[idx];
    float si = xla_sigmoid(ig);
    float sf = xla_sigmoid(fg);
    float so = xla_sigmoid(og);
    float nc = __fadd_rn(__fmul_rn(sf, c), __fmul_rn(si, xla_tanh(gg)));
    float nh = __fmul_rn(so, xla_tanh(nc));
    g_c[idx] = nc;
    g_h[idx] = nh;
    hs[idx] = nh;
}

// ---------------------------------------------------------------------------
// Weight prep: W2 transpose + interleaved gate-weight copies (row 4h+g).
__global__ void prep_kernel(const float* __restrict__ Wmsg,
                            const float* __restrict__ Wih,
                            const float* __restrict__ Whh)
{
    int i = blockIdx.x * blockDim.x + threadIdx.x;
    int stride = gridDim.x * blockDim.x;
    for (int t = i; t < 256 * 256; t += stride) {
        int k = t >> 8, r = t & 255;
        g_W2T[k * 256 + r] = Wmsg[r * 512 + 256 + k];
    }
    for (int t = i; t < 1024 * 256; t += stride) {
        int rp = t >> 8, k = t & 255;
        int h = rp >> 2, g = rp & 3;
        int src = g * 256 + h;
        g_Wxp[t] = Wih[src * 512 + k];
        g_Wmp[t] = Wih[src * 512 + 256 + k];
        g_Whp[t] = Whh[src * 256 + k];
    }
}

// ---------------------------------------------------------------------------
__global__ void gather_init(const float* __restrict__ emb,
                            const int* __restrict__ perm,
                            float* __restrict__ out_lstm_emb)
{
    int gid = blockIdx.x * blockDim.x + threadIdx.x;
    if (gid >= CNH) return;
    int n = gid >> 8, h = gid & 255;
    float v = emb[(size_t)perm[n] * CH + h];
    g_x[gid] = v;
    out_lstm_emb[gid] = v;
    g_h[gid] = v;
    g_c[gid] = v;
    if (n % CK == 0) g_m[gid] = 0.f;   // node 0 never receives messages
}

// ---------------------------------------------------------------------------
// GEMM tile body: 128x128 tile @ (by,bx) of A[M,K] @ B[N,K]^T.
// One sequential fma chain over ascending k per output; FFMA2 lanes bitwise
// == scalar. M-paired accumulators; register double-buffered smem pipeline,
// one __syncthreads per k-tile.
// Cinit != null : acc starts at Cinit (chain prefix).
// Cadd  != null : post-add (commutative).
// EPI == 0: store tile to C. EPI == 1: LSTM epilogue (interleaved gate cols),
//           writes g_c/g_h/hs, no C store.
template<int EPI>
__device__ __forceinline__ void sgemm_tile(
    int K,
    const float* __restrict__ A, int lda,
    const float* __restrict__ Bm, int ldb,
    float* __restrict__ C, int ldc,
    const float* __restrict__ Cinit,
    const float* __restrict__ Cadd,
    int bx, int by,
    float As[2][16][128], float Bs[2][16][128],
    float* __restrict__ hs)
{
    const int tid = threadIdx.x;
    const int tx = tid & 15;
    const int ty = tid >> 4;
    const float* Ab = A + (size_t)by * 128 * lda;
    const float* Bb = Bm + (size_t)bx * 128 * ldb;
    const int lrow = tid >> 1;
    const int lk4b = (tid & 1) * 2;

    u64 acc2[4][8];   // [m-pair][j]; lanes = (row m0, row m1)
    if (Cinit) {
#pragma unroll
        for (int mp = 0; mp < 4; mp++) {
            int lr0 = (mp < 2) ? (ty * 4 + mp * 2) : (64 + ty * 4 + (mp - 2) * 2);
            size_t r0 = (size_t)by * 128 + lr0;
            const float* I0 = Cinit + r0 * ldc + (size_t)bx * 128;
            const float* I1 = I0 + ldc;
            float4 a0 = *(const float4*)(I0 + tx * 4);
            float4 a1 = *(const float4*)(I0 + 64 + tx * 4);
            float4 b0 = *(const float4*)(I1 + tx * 4);
            float4 b1 = *(const float4*)(I1 + 64 + tx * 4);
            acc2[mp][0] = pk2(a0.x, b0.x); acc2[mp][1] = pk2(a0.y, b0.y);
            acc2[mp][2] = pk2(a0.z, b0.z); acc2[mp][3] = pk2(a0.w, b0.w);
            acc2[mp][4] = pk2(a1.x, b1.x); acc2[mp][5] = pk2(a1.y, b1.y);
            acc2[mp][6] = pk2(a1.z, b1.z); acc2[mp][7] = pk2(a1.w, b1.w);
        }
    } else {
#pragma unroll
        for (int mp = 0; mp < 4; mp++)
#pragma unroll
            for (int j = 0; j < 8; j++) acc2[mp][j] = 0ull;
    }

    float4 avs[2], bvs[2];
#pragma unroll
    for (int u = 0; u < 2; u++) {
        int k4 = lk4b + u;
        avs[u] = *(const float4*)(Ab + (size_t)lrow * lda + k4 * 4);
        bvs[u] = *(const float4*)(Bb + (size_t)lrow * ldb + k4 * 4);
    }
#pragma unroll
    for (int u = 0; u < 2; u++) {
        int k4 = lk4b + u;
        As[0][k4 * 4 + 0][lrow] = avs[u].x;
        As[0][k4 * 4 + 1][lrow] = avs[u].y;
        As[0][k4 * 4 + 2][lrow] = avs[u].z;
        As[0][k4 * 4 + 3][lrow] = avs[u].w;
        Bs[0][k4 * 4 + 0][lrow] = bvs[u].x;
        Bs[0][k4 * 4 + 1][lrow] = bvs[u].y;
        Bs[0][k4 * 4 + 2][lrow] = bvs[u].z;
        Bs[0][k4 * 4 + 3][lrow] = bvs[u].w;
    }
    __syncthreads();

    const int T = K >> 4;
    int buf = 0;
    for (int t = 0; t < T; t++) {
        if (t + 1 < T) {
            int kt = (t + 1) * 16;
#pragma unroll
            for (int u = 0; u < 2; u++) {
                int k4 = lk4b + u;
                avs[u] = *(const float4*)(Ab + (size_t)lrow * lda + kt + k4 * 4);
                bvs[u] = *(const float4*)(Bb + (size_t)lrow * ldb + kt + k4 * 4);
            }
        }
#pragma unroll
        for (int k = 0; k < 16; k++) {
            u64 ap[4];
            ap[0] = *(const u64*)(&As[buf][k][ty * 4]);
            ap[1] = *(const u64*)(&As[buf][k][ty * 4 + 2]);
            ap[2] = *(const u64*)(&As[buf][k][64 + ty * 4]);
            ap[3] = *(const u64*)(&As[buf][k][64 + ty * 4 + 2]);
            float b[8];
            *(float4*)(b)     = *(const float4*)(&Bs[buf][k][tx * 4]);
            *(float4*)(b + 4) = *(const float4*)(&Bs[buf][k][64 + tx * 4]);
#pragma unroll
            for (int j = 0; j < 8; j++) {
                u64 bd = pk2(b[j], b[j]);
#pragma unroll
                for (int mp = 0; mp < 4; mp++)
                    acc2[mp][j] = ffma2(ap[mp], bd, acc2[mp][j]);
            }
        }
        if (t + 1 < T) {
            int nb = buf ^ 1;
#pragma unroll
            for (int u = 0; u < 2; u++) {
                int k4 = lk4b + u;
                As[nb][k4 * 4 + 0][lrow] = avs[u].x;
                As[nb][k4 * 4 + 1][lrow] = avs[u].y;
                As[nb][k4 * 4 + 2][lrow] = avs[u].z;
                As[nb][k4 * 4 + 3][lrow] = avs[u].w;
                Bs[nb][k4 * 4 + 0][lrow] = bvs[u].x;
                Bs[nb][k4 * 4 + 1][lrow] = bvs[u].y;
                Bs[nb][k4 * 4 + 2][lrow] = bvs[u].z;
                Bs[nb][k4 * 4 + 3][lrow] = bvs[u].w;
            }
            __syncthreads();
            buf = nb;
        }
    }

#pragma unroll
    for (int mp = 0; mp < 4; mp++) {
        int lr0 = (mp < 2) ? (ty * 4 + mp * 2) : (64 + ty * 4 + (mp - 2) * 2);
        size_t r0 = (size_t)by * 128 + lr0;
        float2 p[8];
#pragma unroll
        for (int j = 0; j < 8; j++) p[j] = up2(acc2[mp][j]);

        if (EPI == 1) {
            // gates tile (interleaved: col = 4h+g) + post-add t2 + LSTM
            const float* A0 = Cadd + r0 * ldc + (size_t)bx * 128;
            const float* A1 = A0 + ldc;
            float4 c00 = *(const float4*)(A0 + tx * 4);
            float4 c01 = *(const float4*)(A0 + 64 + tx * 4);
            float4 c10 = *(const float4*)(A1 + tx * 4);
            float4 c11 = *(const float4*)(A1 + 64 + tx * 4);
            int h0 = bx * 32 + tx;
            int h1 = h0 + 16;
            lstm_cell(r0, h0,
                      __fadd_rn(p[0].x, c00.x), __fadd_rn(p[1].x, c00.y),
                      __fadd_rn(p[2].x, c00.z), __fadd_rn(p[3].x, c00.w), hs);
            lstm_cell(r0 + 1, h0,
                      __fadd_rn(p[0].y, c10.x), __fadd_rn(p[1].y, c10.y),
                      __fadd_rn(p[2].y, c10.z), __fadd_rn(p[3].y, c10.w), hs);
            lstm_cell(r0, h1,
                      __fadd_rn(p[4].x, c01.x), __fadd_rn(p[5].x, c01.y),
                      __fadd_rn(p[6].x, c01.z), __fadd_rn(p[7].x, c01.w), hs);
            lstm_cell(r0 + 1, h1,
                      __fadd_rn(p[4].y, c11.x), __fadd_rn(p[5].y, c11.y),
                      __fadd_rn(p[6].y, c11.z), __fadd_rn(p[7].y, c11.w), hs);
        } else {
            float* C0 = C + r0 * ldc + (size_t)bx * 128;
            float* C1 = C0 + ldc;
            float4 v00 = make_float4(p[0].x, p[1].x, p[2].x, p[3].x);
            float4 v01 = make_float4(p[4].x, p[5].x, p[6].x, p[7].x);
            float4 v10 = make_float4(p[0].y, p[1].y, p[2].y, p[3].y);
            float4 v11 = make_float4(p[4].y, p[5].y, p[6].y, p[7].y);
            if (Cadd) {
                const float* A0 = Cadd + r0 * ldc + (size_t)bx * 128;
                const float* A1 = A0 + ldc;
                float4 c00 = *(const float4*)(A0 + tx * 4);
                float4 c01 = *(const float4*)(A0 + 64 + tx * 4);
                float4 c10 = *(const float4*)(A1 + tx * 4);
                float4 c11 = *(const float4*)(A1 + 64 + tx * 4);
                v00.x = __fadd_rn(v00.x, c00.x); v00.y = __fadd_rn(v00.y, c00.y);
                v00.z = __fadd_rn(v00.z, c00.z); v00.w = __fadd_rn(v00.w, c00.w);
                v01.x = __fadd_rn(v01.x, c01.x); v01.y = __fadd_rn(v01.y, c01.y);
                v01.z = __fadd_rn(v01.z, c01.z); v01.w = __fadd_rn(v01.w, c01.w);
                v10.x = __fadd_rn(v10.x, c10.x); v10.y = __fadd_rn(v10.y, c10.y);
                v10.z = __fadd_rn(v10.z, c10.z); v10.w = __fadd_rn(v10.w, c10.w);
                v11.x = __fadd_rn(v11.x, c11.x); v11.y = __fadd_rn(v11.y, c11.y);
                v11.z = __fadd_rn(v11.z, c11.z); v11.w = __fadd_rn(v11.w, c11.w);
            }
            *(float4*)(C0 + tx * 4) = v00;
            *(float4*)(C0 + 64 + tx * 4) = v01;
            *(float4*)(C1 + tx * 4) = v10;
            *(float4*)(C1 + 64 + tx * 4) = v11;
        }
    }
}

// ---------------------------------------------------------------------------
// Fused pre-msg launch (round-8 structure, interleaved Wh'):
//   blocks 0..799   : t2 = h @ Wh'^T
//   blocks 800..999 : A  = h @ W1^T
__global__ __launch_bounds__(256, 2) void step_pre(const float* __restrict__ Wmsg)
{
    __shared__ float As[2][16][128];
    __shared__ float Bs[2][16][128];
    int bid = blockIdx.x;
    if (bid < 800) {
        sgemm_tile<0>(256, g_h, 256, g_Whp, 256, g_t2, 1024, nullptr, nullptr,
                      bid & 7, bid >> 3, As, Bs, nullptr);
    } else {
        int i = bid - 800;
        sgemm_tile<0>(256, g_h, 256, Wmsg, 512, g_A, 256, nullptr, nullptr,
                      i & 1, i >> 1, As, Bs, nullptr);
    }
}

// gates + LSTM fused (chain prefix gx -> m terms, post-add t2, LSTM epilogue)
__global__ __launch_bounds__(256, 2) void gates_lstm(float* __restrict__ hs_slice)
{
    __shared__ float As[2][16][128];
    __shared__ float Bs[2][16][128];
    sgemm_tile<1>(256, g_m, 256, g_Wmp, 256, nullptr, 1024, g_gx, g_t2,
                  blockIdx.x, blockIdx.y, As, Bs, hs_slice);
}

// plain GEMM (gx, oe)
__global__ __launch_bounds__(256, 2) void sgemm_nt(
    int K,
    const float* __restrict__ A, int lda,
    const float* __restrict__ Bm, int ldb,
    float* __restrict__ C, int ldc)
{
    __shared__ float As[2][16][128];
    __shared__ float Bs[2][16][128];
    sgemm_tile<0>(K, A, lda, Bm, ldb, C, ldc, nullptr, nullptr,
                  blockIdx.x, blockIdx.y, As, Bs, nullptr);
}

// ---------------------------------------------------------------------------
// Exact per-edge msg chains, FFMA2 (at the FFMA2 pipe limit — untouched).
__global__ __launch_bounds__(128) void msg_exact()
{
    __shared__ float hj[256];
    const int j = blockIdx.x;
    const int b = blockIdx.y;
    const int base = b * CK + 1;
    const int rh = threadIdx.x;

    hj[rh]       = g_h[(size_t)(base + j) * CH + rh];
    hj[rh + 128] = g_h[(size_t)(base + j) * CH + rh + 128];
    __syncthreads();

    u64 acc[24];
#pragma unroll
    for (int i = 0; i < 24; i++)
        acc[i] = *(const u64*)(&g_A[(size_t)(base + i) * CH + 2 * rh]);

    const u64* w2p = (const u64*)g_W2T + rh;
#pragma unroll 4
    for (int k = 0; k < 256; k++) {
        u64 w = w2p[(size_t)k * 128];
        float hk = hj[k];
        u64 h2 = pk2(hk, hk);
#pragma unroll
        for (int i = 0; i < 24; i++)
            acc[i] = ffma2(h2, w, acc[i]);
    }

    float mlo = 0.f, mhi = 0.f;
#pragma unroll
    for (int i = 0; i < 24; i++)
        if (i != j) {
            float2 e = up2(acc[i]);
            mlo = __fadd_rn(mlo, fmaxf(e.x, 0.f));
            mhi = __fadd_rn(mhi, fmaxf(e.y, 0.f));
        }
    *(float2*)(&g_m[(size_t)(base + j) * CH + 2 * rh]) = make_float2(mlo, mhi);
}

// ---------------------------------------------------------------------------
__global__ void finalize_emb(float* __restrict__ o_in, float* __restrict__ o_out)
{
    int gid = blockIdx.x * blockDim.x + threadIdx.x;
    if (gid >= CNH) return;
    int n = gid >> 8;
    bool anchor = (n % CK) == 0;
    float xv = g_x[gid];
    float hv = g_h[gid];
    float ov = g_oe[gid];
    o_in[gid]  = anchor ? xv : hv;
    o_out[gid] = anchor ? xv : ov;
}

// ---------------------------------------------------------------------------
__global__ __launch_bounds__(256) void gol_kernel(const float* __restrict__ src, int out_base)
{
    __shared__ float hn[24][257];
    __shared__ float nrm[24];
    __shared__ float red[256];
    const int tid = threadIdx.x;
    const size_t rowbase = (size_t)blockIdx.x * 25 + 1;
    for (int idx = tid; idx < 24 * 256; idx += 256) {
        int i = idx >> 8, k = idx & 255;
        hn[i][k] = src[(rowbase + i) * 256 + k];
    }
    __syncthreads();
    if (tid < 24) {
        float s = 0.f;
        for (int k = 0; k < 256; k++) { float v = hn[tid][k]; s += v * v; }
        nrm[tid] = 1.f / (sqrtf(s) + 1e-8f);
    }
    __syncthreads();
    for (int idx = tid; idx < 24 * 256; idx += 256) {
        int i = idx >> 8, k = idx & 255;
        hn[i][k] *= nrm[i];
    }
    __syncthreads();
    float local = 0.f;
    for (int p = tid; p < 276; p += 256) {
        int i = 0, pp = p;
        while (pp >= 23 - i) { pp -= 23 - i; i++; }
        int j = i + 1 + pp;
        float d = 0.f;
#pragma unroll 8
        for (int k = 0; k < 256; k++) d += hn[i][k] * hn[j][k];
        local += fabsf(d);
    }
    red[tid] = local;
    __syncthreads();
    for (int s = 128; s > 0; s >>= 1) {
        if (tid < s) red[tid] += red[tid + s];
        __syncthreads();
    }
    if (tid == 0) g_red[out_base + blockIdx.x] = red[0] * (2.f / (24.f * 23.f));
}

__global__ void gol_finalize(float* __restrict__ out)
{
    __shared__ double red[256];
    int tid = threadIdx.x;
    double s1 = 0.0, s2 = 0.0;
    for (int i = tid; i < CSTEPS * CB; i += 256) s1 += (double)g_red[i];
    for (int i = tid; i < CB; i += 256) s2 += (double)g_red[CSTEPS * CB + i];
    red[tid] = s1 / (double)(CSTEPS * CB) + s2 / (double)CB;
    __syncthreads();
    for (int s = 128; s > 0; s >>= 1) {
        if (tid < s) red[tid] += red[tid + s];
        __syncthreads();
    }
    if (tid == 0) out[0] = (float)red[0];
}

// ---------------------------------------------------------------------------
extern "C" void kernel_launch(void* const* d_in, const int* in_sizes, int n_in,
                              void* d_out, int out_size)
{
    (void)in_sizes; (void)n_in; (void)out_size;
    const float* emb  = (const float*)d_in[0];
    const float* Wmsg = (const float*)d_in[1];
    const float* Wih  = (const float*)d_in[2];
    const float* Whh  = (const float*)d_in[3];
    const float* Wout = (const float*)d_in[4];
    const int*   perm = (const int*)d_in[5];

    float* out = (float*)d_out;
    float* o_gol  = out;
    float* o_lstm = out + 1;
    float* o_in   = out + 1 + (size_t)CNH;
    float* o_out  = out + 1 + 2 * (size_t)CNH;
    float* o_hs   = out + 1 + 3 * (size_t)CNH;

    float *px, *ph, *pgx, *pWxp, *poe;
    cudaGetSymbolAddress((void**)&px,   g_x);
    cudaGetSymbolAddress((void**)&ph,   g_h);
    cudaGetSymbolAddress((void**)&pgx,  g_gx);
    cudaGetSymbolAddress((void**)&pWxp, g_Wxp);
    cudaGetSymbolAddress((void**)&poe,  g_oe);

    prep_kernel<<<256, 256>>>(Wmsg, Wih, Whh);
    gather_init<<<CNH / 256, 256>>>(emb, perm, o_lstm);

    // gx = x @ Wx'^T  (interleaved cols) — chain prefix of t1, reused each step
    sgemm_nt<<<dim3(8, CN / 128), 256>>>(256, px, 256, pWxp, 256, pgx, 1024);

    for (int s = 0; s < CSTEPS; s++) {
        // fused: t2 = h @ Wh'^T  AND  A = h @ W1^T  (both depend only on h)
        step_pre<<<1000, 256>>>(Wmsg);
        // per-edge exact msg chains
        msg_exact<<<dim3(24, CB), 128>>>();
        // gates(+LSTM): chain(gx -> m terms) + t2, then LSTM in-register
        gates_lstm<<<dim3(8, CN / 128), 256>>>(o_hs + (size_t)s * CNH);
    }

    // output_embeddings = h_last @ W_out^T
    sgemm_nt<<<dim3(2, CN / 128), 256>>>(256, ph, 256, Wout, 256, poe, 256);
    finalize_emb<<<CNH / 256, 256>>>(o_in, o_out);

    gol_kernel<<<CSTEPS * CB, 256>>>(o_hs, 0);
    gol_kernel<<<CB, 256>>>(poe, CSTEPS * CB);
    gol_finalize<<<1, 256>>>(o_gol);
}

// round 14
// speedup vs baseline: 1.1159x; 1.0325x over previous
#include <cuda_runtime.h>
#include <math.h>

// Problem constants
constexpr int CB = 512;        // batch
constexpr int CK = 25;         // nodes per board (incl. anchor node 0)
constexpr int CH = 256;        // hidden
constexpr int CSTEPS = 32;
constexpr int CN = CB * CK;    // 12800 nodes
constexpr int CNH = CN * CH;   // 3276800

// Scratch (device globals; no allocation allowed)
__device__ float g_x[CNH];             // lstm_emb (constant x)
__device__ float g_h[CNH];             // hidden state
__device__ float g_c[CNH];             // cell state
__device__ float g_gx[CN * 1024];      // chain prefix: x @ W_ih[:, :256].T
__device__ float g_A[CNH];             // per-step A = h @ W1^T
__device__ float g_m[CNH];             // per-step messages
__device__ float g_t2[CN * 1024];      // per-step t2 = h @ W_hh^T
__device__ float g_gates[CN * 1024];   // gates
__device__ float g_W2P[256 * 256];     // W2 pair-packed: (k-pair, rh) -> 2x u64 lanes
__device__ float g_oe[CNH];            // output_embeddings
__device__ float g_red[CSTEPS * CB + CB];  // per-block gol partials

// ---------------------------------------------------------------------------
// Packed f32x2 helpers (Blackwell FFMA2) — bitwise identical per lane to scalar.
typedef unsigned long long u64;
__device__ __forceinline__ u64 pk2(float lo, float hi)
{
    u64 r; asm("mov.b64 %0, {%1, %2};" : "=l"(r) : "f"(lo), "f"(hi)); return r;
}
__device__ __forceinline__ float2 up2(u64 v)
{
    float2 f; asm("mov.b64 {%0, %1}, %2;" : "=f"(f.x), "=f"(f.y) : "l"(v)); return f;
}
__device__ __forceinline__ u64 ffma2(u64 a, u64 b, u64 c)
{
    u64 d; asm("fma.rn.f32x2 %0, %1, %2, %3;" : "=l"(d) : "l"(a), "l"(b), "l"(c));
    return d;
}

// ---------------------------------------------------------------------------
// XLA elementwise replicas (EmitFastTanh; logistic = 0.5 + 0.5*tanh(0.5x)).
__device__ __forceinline__ float xla_tanh(float x)
{
    float xc = fminf(fmaxf(x, -9.f), 9.f);
    float x2 = __fmul_rn(xc, xc);
    float np = fmaf(x2, -2.76076847742355e-16f, 2.00018790482477e-13f);
    np = fmaf(x2, np, -8.60467152213735e-11f);
    np = fmaf(x2, np,  5.12229709037114e-08f);
    np = fmaf(x2, np,  1.48572235717979e-05f);
    np = fmaf(x2, np,  6.37261928875436e-04f);
    np = fmaf(x2, np,  4.89352455891786e-03f);
    float num = __fmul_rn(xc, np);
    float dp = fmaf(x2, 1.19825839466702e-06f, 1.18534705686654e-04f);
    dp = fmaf(x2, dp, 2.26843463243900e-03f);
    dp = fmaf(x2, dp, 4.89352518554385e-03f);
    float r = __fdiv_rn(num, dp);
    return (fabsf(x) < 0.0004f) ? x : r;
}
__device__ __forceinline__ float xla_sigmoid(float x)
{
    return __fadd_rn(0.5f, __fmul_rn(0.5f, xla_tanh(__fmul_rn(0.5f, x))));
}

// ---------------------------------------------------------------------------
// W2 pair-packed layout for one-LDG.128-per-2k in msg_exact:
//   float offset of (k, rh, lane) = ((k>>1)*128 + rh)*4 + (k&1)*2 + lane
//   lane 0 -> output r=2rh, lane 1 -> r=2rh+1;  W2[r][k] = Wmsg[r*512+256+k]
__global__ void prep_kernel(const float* __restrict__ Wmsg)
{
    int t = blockIdx.x * blockDim.x + threadIdx.x;
    if (t >= 256 * 128) return;
    int k = t >> 7, rh = t & 127;
    size_t off = ((size_t)(k >> 1) * 128 + rh) * 4 + (k & 1) * 2;
    g_W2P[off]     = Wmsg[(2 * rh)     * 512 + 256 + k];
    g_W2P[off + 1] = Wmsg[(2 * rh + 1) * 512 + 256 + k];
}

// ---------------------------------------------------------------------------
__global__ void gather_init(const float* __restrict__ emb,
                            const int* __restrict__ perm,
                            float* __restrict__ out_lstm_emb)
{
    int gid = blockIdx.x * blockDim.x + threadIdx.x;
    if (gid >= CNH) return;
    int n = gid >> 8, h = gid & 255;
    float v = emb[(size_t)perm[n] * CH + h];
    g_x[gid] = v;
    out_lstm_emb[gid] = v;
    g_h[gid] = v;
    g_c[gid] = v;
    if (n % CK == 0) g_m[gid] = 0.f;   // node 0 never receives messages
}

// ---------------------------------------------------------------------------
// 256-thread GEMM tile (128x128 @ (by,bx)) of A[M,K] @ B[N,K]^T.
// One sequential fma chain over ascending k per output; FFMA2 lanes bitwise
// == scalar. M-paired accumulators; register double-buffered smem pipeline.
// Cinit != null : acc starts at Cinit (chain prefix).
// Cadd  != null : post-add (commutative).
__device__ __forceinline__ void sgemm_tile(
    int K,
    const float* __restrict__ A, int lda,
    const float* __restrict__ Bm, int ldb,
    float* __restrict__ C, int ldc,
    const float* __restrict__ Cinit,
    const float* __restrict__ Cadd,
    int bx, int by,
    float As[2][16][128], float Bs[2][16][128])
{
    const int tid = threadIdx.x;
    const int tx = tid & 15;
    const int ty = tid >> 4;
    const float* Ab = A + (size_t)by * 128 * lda;
    const float* Bb = Bm + (size_t)bx * 128 * ldb;
    const int lrow = tid >> 1;
    const int lk4b = (tid & 1) * 2;

    u64 acc2[4][8];   // [m-pair][j]; lanes = (row m0, row m1)
    if (Cinit) {
#pragma unroll
        for (int mp = 0; mp < 4; mp++) {
            int lr0 = (mp < 2) ? (ty * 4 + mp * 2) : (64 + ty * 4 + (mp - 2) * 2);
            size_t r0 = (size_t)by * 128 + lr0;
            const float* I0 = Cinit + r0 * ldc + (size_t)bx * 128;
            const float* I1 = I0 + ldc;
            float4 a0 = *(const float4*)(I0 + tx * 4);
            float4 a1 = *(const float4*)(I0 + 64 + tx * 4);
            float4 b0 = *(const float4*)(I1 + tx * 4);
            float4 b1 = *(const float4*)(I1 + 64 + tx * 4);
            acc2[mp][0] = pk2(a0.x, b0.x); acc2[mp][1] = pk2(a0.y, b0.y);
            acc2[mp][2] = pk2(a0.z, b0.z); acc2[mp][3] = pk2(a0.w, b0.w);
            acc2[mp][4] = pk2(a1.x, b1.x); acc2[mp][5] = pk2(a1.y, b1.y);
            acc2[mp][6] = pk2(a1.z, b1.z); acc2[mp][7] = pk2(a1.w, b1.w);
        }
    } else {
#pragma unroll
        for (int mp = 0; mp < 4; mp++)
#pragma unroll
            for (int j = 0; j < 8; j++) acc2[mp][j] = 0ull;
    }

    float4 avs[2], bvs[2];
#pragma unroll
    for (int u = 0; u < 2; u++) {
        int k4 = lk4b + u;
        avs[u] = *(const float4*)(Ab + (size_t)lrow * lda + k4 * 4);
        bvs[u] = *(const float4*)(Bb + (size_t)lrow * ldb + k4 * 4);
    }
#pragma unroll
    for (int u = 0; u < 2; u++) {
        int k4 = lk4b + u;
        As[0][k4 * 4 + 0][lrow] = avs[u].x;
        As[0][k4 * 4 + 1][lrow] = avs[u].y;
        As[0][k4 * 4 + 2][lrow] = avs[u].z;
        As[0][k4 * 4 + 3][lrow] = avs[u].w;
        Bs[0][k4 * 4 + 0][lrow] = bvs[u].x;
        Bs[0][k4 * 4 + 1][lrow] = bvs[u].y;
        Bs[0][k4 * 4 + 2][lrow] = bvs[u].z;
        Bs[0][k4 * 4 + 3][lrow] = bvs[u].w;
    }
    __syncthreads();

    const int T = K >> 4;
    int buf = 0;
    for (int t = 0; t < T; t++) {
        if (t + 1 < T) {
            int kt = (t + 1) * 16;
#pragma unroll
            for (int u = 0; u < 2; u++) {
                int k4 = lk4b + u;
                avs[u] = *(const float4*)(Ab + (size_t)lrow * lda + kt + k4 * 4);
                bvs[u] = *(const float4*)(Bb + (size_t)lrow * ldb + kt + k4 * 4);
            }
        }
#pragma unroll
        for (int k = 0; k < 16; k++) {
            u64 ap[4];
            ap[0] = *(const u64*)(&As[buf][k][ty * 4]);
            ap[1] = *(const u64*)(&As[buf][k][ty * 4 + 2]);
            ap[2] = *(const u64*)(&As[buf][k][64 + ty * 4]);
            ap[3] = *(const u64*)(&As[buf][k][64 + ty * 4 + 2]);
            float b[8];
            *(float4*)(b)     = *(const float4*)(&Bs[buf][k][tx * 4]);
            *(float4*)(b + 4) = *(const float4*)(&Bs[buf][k][64 + tx * 4]);
#pragma unroll
            for (int j = 0; j < 8; j++) {
                u64 bd = pk2(b[j], b[j]);
#pragma unroll
                for (int mp = 0; mp < 4; mp++)
                    acc2[mp][j] = ffma2(ap[mp], bd, acc2[mp][j]);
            }
        }
        if (t + 1 < T) {
            int nb = buf ^ 1;
#pragma unroll
            for (int u = 0; u < 2; u++) {
                int k4 = lk4b + u;
                As[nb][k4 * 4 + 0][lrow] = avs[u].x;
                As[nb][k4 * 4 + 1][lrow] = avs[u].y;
                As[nb][k4 * 4 + 2][lrow] = avs[u].z;
                As[nb][k4 * 4 + 3][lrow] = avs[u].w;
                Bs[nb][k4 * 4 + 0][lrow] = bvs[u].x;
                Bs[nb][k4 * 4 + 1][lrow] = bvs[u].y;
                Bs[nb][k4 * 4 + 2][lrow] = bvs[u].z;
                Bs[nb][k4 * 4 + 3][lrow] = bvs[u].w;
            }
            __syncthreads();
            buf = nb;
        }
    }

#pragma unroll
    for (int mp = 0; mp < 4; mp++) {
        int lr0 = (mp < 2) ? (ty * 4 + mp * 2) : (64 + ty * 4 + (mp - 2) * 2);
        size_t r0 = (size_t)by * 128 + lr0;
        float* C0 = C + r0 * ldc + (size_t)bx * 128;
        float* C1 = C0 + ldc;
        float2 p[8];
#pragma unroll
        for (int j = 0; j < 8; j++) p[j] = up2(acc2[mp][j]);
        float4 v00 = make_float4(p[0].x, p[1].x, p[2].x, p[3].x);
        float4 v01 = make_float4(p[4].x, p[5].x, p[6].x, p[7].x);
        float4 v10 = make_float4(p[0].y, p[1].y, p[2].y, p[3].y);
        float4 v11 = make_float4(p[4].y, p[5].y, p[6].y, p[7].y);
        if (Cadd) {
            const float* A0 = Cadd + r0 * ldc + (size_t)bx * 128;
            const float* A1 = A0 + ldc;
            float4 c00 = *(const float4*)(A0 + tx * 4);
            float4 c01 = *(const float4*)(A0 + 64 + tx * 4);
            float4 c10 = *(const float4*)(A1 + tx * 4);
            float4 c11 = *(const float4*)(A1 + 64 + tx * 4);
            v00.x = __fadd_rn(v00.x, c00.x); v00.y = __fadd_rn(v00.y, c00.y);
            v00.z = __fadd_rn(v00.z, c00.z); v00.w = __fadd_rn(v00.w, c00.w);
            v01.x = __fadd_rn(v01.x, c01.x); v01.y = __fadd_rn(v01.y, c01.y);
            v01.z = __fadd_rn(v01.z, c01.z); v01.w = __fadd_rn(v01.w, c01.w);
            v10.x = __fadd_rn(v10.x, c10.x); v10.y = __fadd_rn(v10.y, c10.y);
            v10.z = __fadd_rn(v10.z, c10.z); v10.w = __fadd_rn(v10.w, c10.w);
            v11.x = __fadd_rn(v11.x, c11.x); v11.y = __fadd_rn(v11.y, c11.y);
            v11.z = __fadd_rn(v11.z, c11.z); v11.w = __fadd_rn(v11.w, c11.w);
        }
        *(float4*)(C0 + tx * 4) = v00;
        *(float4*)(C0 + 64 + tx * 4) = v01;
        *(float4*)(C1 + tx * 4) = v10;
        *(float4*)(C1 + 64 + tx * 4) = v11;
    }
}

__global__ __launch_bounds__(256, 2) void sgemm_nt(
    int K,
    const float* __restrict__ A, int lda,
    const float* __restrict__ Bm, int ldb,
    float* __restrict__ C, int ldc,
    const float* __restrict__ Cinit,
    const float* __restrict__ Cadd)
{
    __shared__ float As[2][16][128];
    __shared__ float Bs[2][16][128];
    sgemm_tile(K, A, lda, Bm, ldb, C, ldc, Cinit, Cadd,
               blockIdx.x, blockIdx.y, As, Bs);
}

// Fused pre-msg launch: blocks 0..799 compute t2 = h @ W_hh^T,
// blocks 800..999 compute A = h @ W1^T. Both depend only on h.
__global__ __launch_bounds__(256, 2) void step_pre(
    const float* __restrict__ Whh, const float* __restrict__ Wmsg)
{
    __shared__ float As[2][16][128];
    __shared__ float Bs[2][16][128];
    int bid = blockIdx.x;
    if (bid < 800) {
        sgemm_tile(256, g_h, 256, Whh, 256, g_t2, 1024, nullptr, nullptr,
                   bid & 7, bid >> 3, As, Bs);
    } else {
        int i = bid - 800;
        sgemm_tile(256, g_h, 256, Wmsg, 512, g_A, 256, nullptr, nullptr,
                   i & 1, i >> 1, As, Bs);
    }
}

// ---------------------------------------------------------------------------
// Exact per-edge msg chains, FFMA2, k processed in pairs:
// one LDG.128 (two k's of W2 pairs) + one LDS.128 (two duplicated h values)
// per 2 k's -> issue overhead drops from 12.5% to ~4% over the FFMA2 floor.
// Chain per output r: acc = A_i[r]; k ascending (k, then k+1) — identical
// association, FFMA2 lanes bitwise == scalar.
__global__ __launch_bounds__(128) void msg_exact()
{
    __shared__ u64 hj2[256];               // duplicated lanes: (h[k], h[k])
    const int j = blockIdx.x;
    const int b = blockIdx.y;
    const int base = b * CK + 1;
    const int rh = threadIdx.x;

    {
        float v0 = g_h[(size_t)(base + j) * CH + rh];
        float v1 = g_h[(size_t)(base + j) * CH + rh + 128];
        hj2[rh] = pk2(v0, v0);
        hj2[rh + 128] = pk2(v1, v1);
    }
    __syncthreads();

    u64 acc[24];
#pragma unroll
    for (int i = 0; i < 24; i++)
        acc[i] = *(const u64*)(&g_A[(size_t)(base + i) * CH + 2 * rh]);

    // W2P: ulonglong2 index (kp*128 + rh) holds (w_k, w_{k+1}) for outputs
    // (2rh, 2rh+1)
    const ulonglong2* wp = (const ulonglong2*)g_W2P + rh;
#pragma unroll 2
    for (int kp = 0; kp < 128; kp++) {
        ulonglong2 w = wp[(size_t)kp * 128];
        ulonglong2 h = *(const ulonglong2*)(&hj2[2 * kp]);
#pragma unroll
        for (int i = 0; i < 24; i++) {
            acc[i] = ffma2(h.x, w.x, acc[i]);   // k = 2kp
            acc[i] = ffma2(h.y, w.y, acc[i]);   // k = 2kp+1
        }
    }

    float mlo = 0.f, mhi = 0.f;
#pragma unroll
    for (int i = 0; i < 24; i++)
        if (i != j) {
            float2 e = up2(acc[i]);
            mlo = __fadd_rn(mlo, fmaxf(e.x, 0.f));
            mhi = __fadd_rn(mhi, fmaxf(e.y, 0.f));
        }
    *(float2*)(&g_m[(size_t)(base + j) * CH + 2 * rh]) = make_float2(mlo, mhi);
}

// ---------------------------------------------------------------------------
// LSTM pointwise, float4-vectorized on internal buffers; scalar stores to the
// (4B-aligned) output slice.
__global__ void lstm_step(float* __restrict__ hs_slice)
{
    int t = blockIdx.x * blockDim.x + threadIdx.x;
    if (t >= CNH / 4) return;
    int n = t >> 6;
    int h4 = t & 63;
    const float4* g = (const float4*)(g_gates + (size_t)n * 1024);
    float4 ig = g[h4], fg = g[64 + h4], gg = g[128 + h4], og = g[192 + h4];
    float4 c = *(const float4*)(g_c + (size_t)t * 4);
    float4 nc, nh;
    {
        float si = xla_sigmoid(ig.x), sf = xla_sigmoid(fg.x), so = xla_sigmoid(og.x);
        nc.x = __fadd_rn(__fmul_rn(sf, c.x), __fmul_rn(si, xla_tanh(gg.x)));
        nh.x = __fmul_rn(so, xla_tanh(nc.x));
    }
    {
        float si = xla_sigmoid(ig.y), sf = xla_sigmoid(fg.y), so = xla_sigmoid(og.y);
        nc.y = __fadd_rn(__fmul_rn(sf, c.y), __fmul_rn(si, xla_tanh(gg.y)));
        nh.y = __fmul_rn(so, xla_tanh(nc.y));
    }
    {
        float si = xla_sigmoid(ig.z), sf = xla_sigmoid(fg.z), so = xla_sigmoid(og.z);
        nc.z = __fadd_rn(__fmul_rn(sf, c.z), __fmul_rn(si, xla_tanh(gg.z)));
        nh.z = __fmul_rn(so, xla_tanh(nc.z));
    }
    {
        float si = xla_sigmoid(ig.w), sf = xla_sigmoid(fg.w), so = xla_sigmoid(og.w);
        nc.w = __fadd_rn(__fmul_rn(sf, c.w), __fmul_rn(si, xla_tanh(gg.w)));
        nh.w = __fmul_rn(so, xla_tanh(nc.w));
    }
    *(float4*)(g_c + (size_t)t * 4) = nc;
    *(float4*)(g_h + (size_t)t * 4) = nh;
    float* hp = hs_slice + (size_t)t * 4;
    hp[0] = nh.x; hp[1] = nh.y; hp[2] = nh.z; hp[3] = nh.w;
}

// ---------------------------------------------------------------------------
__global__ void finalize_emb(float* __restrict__ o_in, float* __restrict__ o_out)
{
    int gid = blockIdx.x * blockDim.x + threadIdx.x;
    if (gid >= CNH) return;
    int n = gid >> 8;
    bool anchor = (n % CK) == 0;
    float xv = g_x[gid];
    float hv = g_h[gid];
    float ov = g_oe[gid];
    o_in[gid]  = anchor ? xv : hv;
    o_out[gid] = anchor ? xv : ov;
}

// ---------------------------------------------------------------------------
__global__ __launch_bounds__(256) void gol_kernel(const float* __restrict__ src, int out_base)
{
    __shared__ float hn[24][257];
    __shared__ float nrm[24];
    __shared__ float red[256];
    const int tid = threadIdx.x;
    const size_t rowbase = (size_t)blockIdx.x * 25 + 1;
    for (int idx = tid; idx < 24 * 256; idx += 256) {
        int i = idx >> 8, k = idx & 255;
        hn[i][k] = src[(rowbase + i) * 256 + k];
    }
    __syncthreads();
    if (tid < 24) {
        float s = 0.f;
        for (int k = 0; k < 256; k++) { float v = hn[tid][k]; s += v * v; }
        nrm[tid] = 1.f / (sqrtf(s) + 1e-8f);
    }
    __syncthreads();
    for (int idx = tid; idx < 24 * 256; idx += 256) {
        int i = idx >> 8, k = idx & 255;
        hn[i][k] *= nrm[i];
    }
    __syncthreads();
    float local = 0.f;
    for (int p = tid; p < 276; p += 256) {
        int i = 0, pp = p;
        while (pp >= 23 - i) { pp -= 23 - i; i++; }
        int j = i + 1 + pp;
        float d = 0.f;
#pragma unroll 8
        for (int k = 0; k < 256; k++) d += hn[i][k] * hn[j][k];
        local += fabsf(d);
    }
    red[tid] = local;
    __syncthreads();
    for (int s = 128; s > 0; s >>= 1) {
        if (tid < s) red[tid] += red[tid + s];
        __syncthreads();
    }
    if (tid == 0) g_red[out_base + blockIdx.x] = red[0] * (2.f / (24.f * 23.f));
}

__global__ void gol_finalize(float* __restrict__ out)
{
    __shared__ double red[256];
    int tid = threadIdx.x;
    double s1 = 0.0, s2 = 0.0;
    for (int i = tid; i < CSTEPS * CB; i += 256) s1 += (double)g_red[i];
    for (int i = tid; i < CB; i += 256) s2 += (double)g_red[CSTEPS * CB + i];
    red[tid] = s1 / (double)(CSTEPS * CB) + s2 / (double)CB;
    __syncthreads();
    for (int s = 128; s > 0; s >>= 1) {
        if (tid < s) red[tid] += red[tid + s];
        __syncthreads();
    }
    if (tid == 0) out[0] = (float)red[0];
}

// ---------------------------------------------------------------------------
extern "C" void kernel_launch(void* const* d_in, const int* in_sizes, int n_in,
                              void* d_out, int out_size)
{
    (void)in_sizes; (void)n_in; (void)out_size;
    const float* emb  = (const float*)d_in[0];
    const float* Wmsg = (const float*)d_in[1];
    const float* Wih  = (const float*)d_in[2];
    const float* Whh  = (const float*)d_in[3];
    const float* Wout = (const float*)d_in[4];
    const int*   perm = (const int*)d_in[5];

    float* out = (float*)d_out;
    float* o_gol  = out;
    float* o_lstm = out + 1;
    float* o_in   = out + 1 + (size_t)CNH;
    float* o_out  = out + 1 + 2 * (size_t)CNH;
    float* o_hs   = out + 1 + 3 * (size_t)CNH;

    float *px, *ph, *pgx, *pm, *pt2, *pgates, *poe;
    cudaGetSymbolAddress((void**)&px,     g_x);
    cudaGetSymbolAddress((void**)&ph,     g_h);
    cudaGetSymbolAddress((void**)&pgx,    g_gx);
    cudaGetSymbolAddress((void**)&pm,     g_m);
    cudaGetSymbolAddress((void**)&pt2,    g_t2);
    cudaGetSymbolAddress((void**)&pgates, g_gates);
    cudaGetSymbolAddress((void**)&poe,    g_oe);

    prep_kernel<<<128, 256>>>(Wmsg);
    gather_init<<<CNH / 256, 256>>>(emb, perm, o_lstm);

    // gx = x @ W_ih[:, :256]^T  — chain prefix of t1, reused every step
    sgemm_nt<<<dim3(8, CN / 128), 256>>>(256, px, 256, Wih, 512,
                                         pgx, 1024, nullptr, nullptr);

    for (int s = 0; s < CSTEPS; s++) {
        // fused: t2 = h @ W_hh^T  AND  A = h @ W1^T  (both depend only on h)
        step_pre<<<1000, 256>>>(Whh, Wmsg);
        // per-edge exact msg chains (paired-k inner loop)
        msg_exact<<<dim3(24, CB), 128>>>();
        // gates = chain(gx -> m terms) + t2   (post-add, commutative)
        sgemm_nt<<<dim3(8, CN / 128), 256>>>(256, pm, 256, Wih + 256, 512,
                                             pgates, 1024, pgx, pt2);
        lstm_step<<<CNH / 1024, 256>>>(o_hs + (size_t)s * CNH);
    }

    // output_embeddings = h_last @ W_out^T
    sgemm_nt<<<dim3(2, CN / 128), 256>>>(256, ph, 256, Wout, 256,
                                         poe, 256, nullptr, nullptr);
    finalize_emb<<<CNH / 256, 256>>>(o_in, o_out);

    gol_kernel<<<CSTEPS * CB, 256>>>(o_hs, 0);
    gol_kernel<<<CB, 256>>>(poe, CSTEPS * CB);
    gol_finalize<<<1, 256>>>(o_gol);
}